// round 1
// baseline (speedup 1.0000x reference)
#include <cuda_runtime.h>

#define NN 10000
#define FI 256
#define FO 64
#define ALPHAS 0.2f

#define BM 64
#define BN 128
#define NSPLIT 4
#define RT 157              // ceil(NN / BM)
#define PST 132             // P tile stride (pad 4 floats: float4-aligned, conflict-free)
#define JCH (NN / NSPLIT)   // 2500, multiple of 4 (int4-aligned adj loads)

// Scratch (static device globals: no allocation allowed)
__device__ float g_Wh[NN * FO];
__device__ float g_f1[NN];
__device__ float g_f2[NN];
__device__ float g_pacc[(size_t)NSPLIT * RT * BM * FO];
__device__ float g_pden[NSPLIT * RT * BM];

// ---- packed f32x2 helpers (FFMA2 only reachable via PTX) ----
__device__ __forceinline__ unsigned long long pk2(float x, float y) {
    unsigned long long r;
    asm("mov.b64 %0, {%1, %2};" : "=l"(r) : "f"(x), "f"(y));
    return r;
}
__device__ __forceinline__ void fma2(unsigned long long& d, unsigned long long a,
                                     unsigned long long b) {
    asm("fma.rn.f32x2 %0, %1, %2, %0;" : "+l"(d) : "l"(a), "l"(b));
}
__device__ __forceinline__ float2 upk2(unsigned long long v) {
    float2 r;
    asm("mov.b64 {%0, %1}, %2;" : "=f"(r.x), "=f"(r.y) : "l"(v));
    return r;
}

// ---------------- Kernel 1: Wh = h @ W ----------------
__global__ __launch_bounds__(256) void wh_kernel(const float* __restrict__ h,
                                                 const float* __restrict__ W) {
    __shared__ float sh[16 * FI];
    int row0 = blockIdx.x * 16;
    const float* hp = h + (long long)row0 * FI;
    for (int t = threadIdx.x; t < 16 * FI; t += 256) sh[t] = hp[t];
    __syncthreads();
    int c = threadIdx.x & 63;
    int ty = threadIdx.x >> 6;  // 0..3 -> rows ty*4..ty*4+3
    float a0 = 0.f, a1 = 0.f, a2 = 0.f, a3 = 0.f;
    for (int k = 0; k < FI; ++k) {
        float w = W[k * FO + c];
        a0 += sh[(ty * 4 + 0) * FI + k] * w;
        a1 += sh[(ty * 4 + 1) * FI + k] * w;
        a2 += sh[(ty * 4 + 2) * FI + k] * w;
        a3 += sh[(ty * 4 + 3) * FI + k] * w;
    }
    g_Wh[(row0 + ty * 4 + 0) * FO + c] = a0;
    g_Wh[(row0 + ty * 4 + 1) * FO + c] = a1;
    g_Wh[(row0 + ty * 4 + 2) * FO + c] = a2;
    g_Wh[(row0 + ty * 4 + 3) * FO + c] = a3;
}

// ---------------- Kernel 2: f1 = Wh@a1, f2 = Wh@a2 (one warp / row) --------
__global__ __launch_bounds__(128) void f12_kernel(const float* __restrict__ a) {
    int row = blockIdx.x * 4 + (threadIdx.x >> 5);
    int lane = threadIdx.x & 31;
    float w0 = g_Wh[row * FO + lane];
    float w1 = g_Wh[row * FO + 32 + lane];
    float s1 = w0 * a[lane] + w1 * a[lane + 32];
    float s2 = w0 * a[FO + lane] + w1 * a[FO + 32 + lane];
    #pragma unroll
    for (int o = 16; o > 0; o >>= 1) {
        s1 += __shfl_xor_sync(0xffffffffu, s1, o);
        s2 += __shfl_xor_sync(0xffffffffu, s2, o);
    }
    if (lane == 0) { g_f1[row] = s1; g_f2[row] = s2; }
}

// ---------------- Kernel 3: fused masked-softmax @ Wh (partials) -----------
// grid (RT, NSPLIT); CTA = 64 rows x one j-chunk of 2500 cols.
__global__ __launch_bounds__(256) void gat_kernel(const int* __restrict__ adj) {
    extern __shared__ float smem[];
    float* sP   = smem;                 // BM*PST
    float* sWh  = sP + BM * PST;        // BN*FO
    float* sf2  = sWh + BN * FO;        // BN
    float* sf1  = sf2 + BN;             // BM
    float* sden = sf1 + BM;             // BM

    const int mt = blockIdx.x;
    const int jq = blockIdx.y;
    const int i0 = mt * BM;
    const int jbeg = jq * JCH;
    const int jend = jbeg + JCH;

    const int tid = threadIdx.x;
    const int warp = tid >> 5, lane = tid & 31;
    const int ti = tid >> 4, tn = tid & 15;  // warp holds ti in {2w, 2w+1}

    if (tid < BM) {
        int i = i0 + tid;
        sf1[tid] = (i < NN) ? g_f1[i] : 0.f;
        sden[tid] = 0.f;
    }

    unsigned long long acc[4][2];
    #pragma unroll
    for (int m = 0; m < 4; ++m) { acc[m][0] = 0ull; acc[m][1] = 0ull; }

    for (int j0 = jbeg; j0 < jend; j0 += BN) {
        __syncthreads();  // previous matmul done consuming sP/sWh
        // stage Wh tile [BN][FO]
        #pragma unroll
        for (int t = 0; t < (BN * FO / 4) / 256; ++t) {
            int f4 = tid + t * 256;
            int row = f4 >> 4, c4 = f4 & 15;
            int j = j0 + row;
            float4 v = make_float4(0.f, 0.f, 0.f, 0.f);
            if (j < jend) v = *(const float4*)&g_Wh[j * FO + c4 * 4];
            *(float4*)&sWh[row * FO + c4 * 4] = v;
        }
        if (tid < BN) {
            int j = j0 + tid;
            sf2[tid] = (j < jend) ? g_f2[j] : 0.f;
        }
        __syncthreads();

        // generate P tile: warp w owns rows w, w+8, ..., w+56
        #pragma unroll
        for (int rr = 0; rr < BM / 8; ++rr) {
            int rl = rr * 8 + warp;
            int i = i0 + rl;
            float f1v = sf1[rl];
            int jb = j0 + lane * 4;
            float4 p = make_float4(0.f, 0.f, 0.f, 0.f);
            if (i < NN) {
                if (jb + 3 < jend) {
                    int4 m4 = *(const int4*)&adj[(long long)i * NN + jb];
                    float s;
                    s = f1v + sf2[lane * 4 + 0]; s = s > 0.f ? s : ALPHAS * s; p.x = m4.x ? __expf(s) : 0.f;
                    s = f1v + sf2[lane * 4 + 1]; s = s > 0.f ? s : ALPHAS * s; p.y = m4.y ? __expf(s) : 0.f;
                    s = f1v + sf2[lane * 4 + 2]; s = s > 0.f ? s : ALPHAS * s; p.z = m4.z ? __expf(s) : 0.f;
                    s = f1v + sf2[lane * 4 + 3]; s = s > 0.f ? s : ALPHAS * s; p.w = m4.w ? __expf(s) : 0.f;
                } else {
                    float* pp = (float*)&p;
                    #pragma unroll
                    for (int c = 0; c < 4; ++c) {
                        int j = jb + c;
                        if (j < jend && adj[(long long)i * NN + j]) {
                            float s = f1v + sf2[lane * 4 + c];
                            s = s > 0.f ? s : ALPHAS * s;
                            pp[c] = __expf(s);
                        }
                    }
                }
            }
            *(float4*)&sP[rl * PST + lane * 4] = p;
            float ps = p.x + p.y + p.z + p.w;
            #pragma unroll
            for (int o = 16; o > 0; o >>= 1) ps += __shfl_xor_sync(0xffffffffu, ps, o);
            if (lane == 0) sden[rl] += ps;  // single owner warp per row: no race
        }
        __syncthreads();

        // C[BM][FO] += P[BM][BN] @ Wh[BN][FO], f32x2-packed
        const float* p0 = sP + (ti + 0) * PST;
        const float* p1 = sP + (ti + 16) * PST;
        const float* p2 = sP + (ti + 32) * PST;
        const float* p3 = sP + (ti + 48) * PST;
        const float* wb = sWh + tn * 4;
        #pragma unroll 4
        for (int k = 0; k < BN; ++k) {
            ulonglong2 w = *(const ulonglong2*)(wb + k * FO);
            unsigned long long q0 = pk2(p0[k], p0[k]);
            unsigned long long q1 = pk2(p1[k], p1[k]);
            unsigned long long q2 = pk2(p2[k], p2[k]);
            unsigned long long q3 = pk2(p3[k], p3[k]);
            fma2(acc[0][0], q0, w.x); fma2(acc[0][1], q0, w.y);
            fma2(acc[1][0], q1, w.x); fma2(acc[1][1], q1, w.y);
            fma2(acc[2][0], q2, w.x); fma2(acc[2][1], q2, w.y);
            fma2(acc[3][0], q3, w.x); fma2(acc[3][1], q3, w.y);
        }
    }
    __syncthreads();

    // write deterministic partials
    float* pa = g_pacc + (size_t)(jq * RT + mt) * BM * FO;
    #pragma unroll
    for (int m = 0; m < 4; ++m) {
        int row = ti + 16 * m;
        float2 v0 = upk2(acc[m][0]);
        float2 v1 = upk2(acc[m][1]);
        float4 o = make_float4(v0.x, v0.y, v1.x, v1.y);
        *(float4*)&pa[row * FO + tn * 4] = o;
    }
    if (tid < BM) g_pden[(jq * RT + mt) * BM + tid] = sden[tid];
}

// ---------------- Kernel 4: combine partials + ELU ----------------
__global__ __launch_bounds__(256) void combine_kernel(float* __restrict__ out) {
    int idx = blockIdx.x * 256 + threadIdx.x;
    if (idx >= NN * FO) return;
    int i = idx >> 6, c = idx & 63;
    int mt = i / BM, row = i % BM;
    float a = 0.f, d = 0.f;
    #pragma unroll
    for (int q = 0; q < NSPLIT; ++q) {
        a += g_pacc[(size_t)(q * RT + mt) * BM * FO + row * FO + c];
        d += g_pden[(q * RT + mt) * BM + row];
    }
    float v = a / d;
    out[idx] = v > 0.f ? v : expm1f(v);
}

extern "C" void kernel_launch(void* const* d_in, const int* in_sizes, int n_in,
                              void* d_out, int out_size) {
    const float* h   = (const float*)d_in[0];
    const int*   adj = (const int*)d_in[1];
    const float* W   = (const float*)d_in[2];
    const float* a   = (const float*)d_in[3];
    float* out = (float*)d_out;

    wh_kernel<<<NN / 16, 256>>>(h, W);
    f12_kernel<<<NN / 4, 128>>>(a);

    int smem_bytes = (BM * PST + BN * FO + BN + BM + BM) * (int)sizeof(float);
    cudaFuncSetAttribute(gat_kernel, cudaFuncAttributeMaxDynamicSharedMemorySize,
                         smem_bytes);
    gat_kernel<<<dim3(RT, NSPLIT), 256, smem_bytes>>>(adj);

    combine_kernel<<<(NN * FO + 255) / 256, 256>>>(out);
}

// round 3
// speedup vs baseline: 1.8283x; 1.8283x over previous
#include <cuda_runtime.h>
#include <cuda_bf16.h>

#define NN 10000
#define FI 256
#define FO 64
#define BM 128
#define BN 64
#define NSPLIT 8
#define RT 79          // ceil(NN/BM)
#define NT 157         // ceil(NN/BN)
#define ALPHAS 0.2f

// ---------------- device scratch (no allocation allowed) ----------------
__device__ float g_Wh[NN * FO];
__device__ __nv_bfloat16 g_WhT_hi[(size_t)FO * NN];
__device__ __nv_bfloat16 g_WhT_lo[(size_t)FO * NN];
__device__ float g_f1[NN];
__device__ float g_f2[NN];
__device__ float g_pacc[(size_t)NSPLIT * RT * BM * FO];
__device__ float g_pden[NSPLIT * RT * BM];

// ---------------- smem layout (bytes) ----------------
// P rows padded to 144B (72 bf16) -> conflict-free ldmatrix
#define PSTB 144
#define SM_F2   0            // 64 floats
#define SM_DEN  256          // 128 floats
#define SM_PHI  768          // 128 * 144
#define SM_PLO  (SM_PHI + BM * PSTB)            // 19200
#define SM_BHI  (SM_PLO + BM * PSTB)            // 37632
#define SM_BLO  (SM_BHI + FO * PSTB)            // 46848
#define SM_TOTAL (SM_BLO + FO * PSTB)           // 56064

// ---------------- PTX helpers ----------------
__device__ __forceinline__ unsigned s2u(const void* p) {
    unsigned a;
    asm("{ .reg .u64 t; cvta.to.shared.u64 t, %1; cvt.u32.u64 %0, t; }"
        : "=r"(a) : "l"(p));
    return a;
}
__device__ __forceinline__ void ldsm4(unsigned* r, unsigned addr) {
    asm volatile("ldmatrix.sync.aligned.m8n8.x4.shared.b16 {%0,%1,%2,%3}, [%4];"
                 : "=r"(r[0]), "=r"(r[1]), "=r"(r[2]), "=r"(r[3]) : "r"(addr));
}
__device__ __forceinline__ void hmma(float* c, const unsigned* a, const unsigned* b) {
    asm volatile(
        "mma.sync.aligned.m16n8k16.row.col.f32.bf16.bf16.f32 "
        "{%0,%1,%2,%3}, {%4,%5,%6,%7}, {%8,%9}, {%0,%1,%2,%3};"
        : "+f"(c[0]), "+f"(c[1]), "+f"(c[2]), "+f"(c[3])
        : "r"(a[0]), "r"(a[1]), "r"(a[2]), "r"(a[3]), "r"(b[0]), "r"(b[1]));
}

// ---------------- Kernel 1: Wh = h @ W  (+ bf16-split Wh^T) ----------------
__global__ __launch_bounds__(256) void wh_kernel(const float* __restrict__ h,
                                                 const float* __restrict__ W) {
    __shared__ float sh[16 * FI];
    int row0 = blockIdx.x * 16;
    const float* hp = h + (long long)row0 * FI;
    for (int t = threadIdx.x; t < 16 * FI; t += 256) sh[t] = hp[t];
    __syncthreads();
    int c = threadIdx.x & 63;
    int ty = threadIdx.x >> 6;   // 4 consecutive rows per thread
    float acc[4] = {0.f, 0.f, 0.f, 0.f};
    for (int k = 0; k < FI; ++k) {
        float w = W[k * FO + c];
        acc[0] += sh[(ty * 4 + 0) * FI + k] * w;
        acc[1] += sh[(ty * 4 + 1) * FI + k] * w;
        acc[2] += sh[(ty * 4 + 2) * FI + k] * w;
        acc[3] += sh[(ty * 4 + 3) * FI + k] * w;
    }
    __nv_bfloat16 hb[4], lb[4];
    #pragma unroll
    for (int q = 0; q < 4; ++q) {
        int row = row0 + ty * 4 + q;
        float v = acc[q];
        g_Wh[row * FO + c] = v;
        hb[q] = __float2bfloat16(v);
        lb[q] = __float2bfloat16(v - __bfloat162float(hb[q]));
    }
    size_t off = (size_t)c * NN + row0 + ty * 4;   // 4 consecutive j -> 8B store
    *(uint2*)&g_WhT_hi[off] = *(uint2*)hb;
    *(uint2*)&g_WhT_lo[off] = *(uint2*)lb;
}

// ---------------- Kernel 2: f1/f2 ----------------
__global__ __launch_bounds__(128) void f12_kernel(const float* __restrict__ a) {
    int row = blockIdx.x * 4 + (threadIdx.x >> 5);
    int lane = threadIdx.x & 31;
    float w0 = g_Wh[row * FO + lane];
    float w1 = g_Wh[row * FO + 32 + lane];
    float s1 = w0 * a[lane] + w1 * a[lane + 32];
    float s2 = w0 * a[FO + lane] + w1 * a[FO + 32 + lane];
    #pragma unroll
    for (int o = 16; o > 0; o >>= 1) {
        s1 += __shfl_xor_sync(0xffffffffu, s1, o);
        s2 += __shfl_xor_sync(0xffffffffu, s2, o);
    }
    if (lane == 0) { g_f1[row] = s1; g_f2[row] = s2; }
}

// ---------------- Kernel 3: fused P-gen + mma.sync GEMM ----------------
__global__ __launch_bounds__(256, 2) void gat_mma(const int* __restrict__ adj) {
    extern __shared__ char smem[];
    const unsigned sb = s2u(smem);
    float* sf2 = (float*)(smem + SM_F2);
    float* sden = (float*)(smem + SM_DEN);

    const int tid = threadIdx.x, wid = tid >> 5, lane = tid & 31;
    const int mt = blockIdx.x, jq = blockIdx.y;
    const int i0 = mt * BM;

    // P-gen mapping: thread -> (row r, 32-col half hh)
    const int r = tid >> 1, hh = tid & 1;
    const int i = i0 + r;
    const bool rowok = (i < NN);
    const float f1v = rowok ? g_f1[i] : 0.f;
    const int* arow = adj + (size_t)i * NN;

    // B-stage mapping: thread -> (c row, 16-elem segment)
    const int bc = tid >> 2, bseg = tid & 3;

    // MMA fragment addressing
    const int m0 = wid * 16;
    const unsigned a_addr = sb + SM_PHI +
        (m0 + (lane & 7) + ((lane >> 3) & 1) * 8) * PSTB + (lane >> 4) * 16;
    const unsigned b_addr = sb + SM_BHI +
        ((lane & 7) + ((lane >> 4) & 1) * 8) * PSTB + ((lane >> 3) & 1) * 16;

    float acc[8][4];
    #pragma unroll
    for (int nt = 0; nt < 8; ++nt)
        #pragma unroll
        for (int q = 0; q < 4; ++q) acc[nt][q] = 0.f;

    if (tid < BM) sden[tid] = 0.f;

    for (int t = jq; t < NT; t += NSPLIT) {
        const int j0 = t * BN;

        // ---- prefetch adj (registers only; overlaps prev tile's MMA) ----
        const int jb = j0 + hh * 32;
        int4 m[8];
        #pragma unroll
        for (int u = 0; u < 8; ++u) {
            bool ok = rowok && (jb + u * 4 + 3 < NN);
            m[u] = ok ? *(const int4*)(arow + jb + u * 4) : make_int4(0, 0, 0, 0);
        }

        __syncthreads();   // prev MMA done reading sP/sB

        // ---- stage B tiles (WhT hi/lo, n-major, padded rows) + f2 ----
        #pragma unroll
        for (int ch = 0; ch < 2; ++ch) {
            int e0 = bseg * 16 + ch * 8;
            uint4 vh = make_uint4(0, 0, 0, 0), vl = make_uint4(0, 0, 0, 0);
            if (j0 + e0 + 7 < NN) {
                size_t off = (size_t)bc * NN + j0 + e0;
                vh = *(const uint4*)(g_WhT_hi + off);
                vl = *(const uint4*)(g_WhT_lo + off);
            }
            int sB = bc * PSTB + e0 * 2;
            *(uint4*)(smem + SM_BHI + sB) = vh;
            *(uint4*)(smem + SM_BLO + sB) = vl;
        }
        if (tid < BN) sf2[tid] = (j0 + tid < NN) ? g_f2[j0 + tid] : 0.f;
        __syncthreads();

        // ---- generate P tile (hi/lo bf16 split) ----
        float rsum = 0.f;
        #pragma unroll
        for (int u = 0; u < 8; ++u) {
            float p[4];
            #pragma unroll
            for (int c4 = 0; c4 < 4; ++c4) {
                float s = f1v + sf2[hh * 32 + u * 4 + c4];
                s = fmaxf(s, ALPHAS * s);            // LeakyReLU
                float e = __expf(s);
                p[c4] = (&m[u].x)[c4] ? e : 0.f;
            }
            rsum += (p[0] + p[1]) + (p[2] + p[3]);
            __nv_bfloat162 h01 = __floats2bfloat162_rn(p[0], p[1]);
            __nv_bfloat162 h23 = __floats2bfloat162_rn(p[2], p[3]);
            unsigned hb01 = *(unsigned*)&h01, hb23 = *(unsigned*)&h23;
            float r0 = __uint_as_float(hb01 << 16);
            float r1 = __uint_as_float(hb01 & 0xffff0000u);
            float r2 = __uint_as_float(hb23 << 16);
            float r3 = __uint_as_float(hb23 & 0xffff0000u);
            __nv_bfloat162 l01 = __floats2bfloat162_rn(p[0] - r0, p[1] - r1);
            __nv_bfloat162 l23 = __floats2bfloat162_rn(p[2] - r2, p[3] - r3);
            int sa = r * PSTB + hh * 64 + u * 8;
            *(uint2*)(smem + SM_PHI + sa) = make_uint2(hb01, hb23);
            *(uint2*)(smem + SM_PLO + sa) = make_uint2(*(unsigned*)&l01, *(unsigned*)&l23);
        }
        rsum += __shfl_down_sync(0xffffffffu, rsum, 1);
        if (!hh) sden[r] += rsum;   // unique owner thread per row
        __syncthreads();

        // ---- MMA: C += P_hi*B_hi + P_hi*B_lo + P_lo*B_hi ----
        #pragma unroll
        for (int ks = 0; ks < 4; ++ks) {
            unsigned ah[4], al[4];
            ldsm4(ah, a_addr + ks * 32);
            ldsm4(al, a_addr + ks * 32 + (SM_PLO - SM_PHI));
            unsigned bh[16], bl[16];
            #pragma unroll
            for (int q = 0; q < 4; ++q) {
                unsigned ba = b_addr + q * 16 * PSTB + ks * 32;
                ldsm4(bh + 4 * q, ba);
                ldsm4(bl + 4 * q, ba + (SM_BLO - SM_BHI));
            }
            #pragma unroll
            for (int nt = 0; nt < 8; ++nt) {
                hmma(acc[nt], ah, bh + nt * 2);
                hmma(acc[nt], ah, bl + nt * 2);
                hmma(acc[nt], al, bh + nt * 2);
            }
        }
    }
    __syncthreads();

    // ---- epilogue: write register partials ----
    {
        float* pa = g_pacc + (size_t)(jq * RT + mt) * BM * FO;
        int row = m0 + (lane >> 2);
        int col = (lane & 3) * 2;
        #pragma unroll
        for (int nt = 0; nt < 8; ++nt) {
            *(float2*)&pa[row * FO + nt * 8 + col] = make_float2(acc[nt][0], acc[nt][1]);
            *(float2*)&pa[(row + 8) * FO + nt * 8 + col] = make_float2(acc[nt][2], acc[nt][3]);
        }
    }
    if (tid < BM) g_pden[(jq * RT + mt) * BM + tid] = sden[tid];
}

// ---------------- Kernel 4: combine partials + ELU ----------------
__global__ __launch_bounds__(256) void combine_kernel(float* __restrict__ out) {
    int idx = blockIdx.x * 256 + threadIdx.x;
    if (idx >= NN * FO) return;
    int i = idx >> 6, c = idx & 63;
    int mt = i >> 7, row = i & 127;
    float a = 0.f, d = 0.f;
    #pragma unroll
    for (int q = 0; q < NSPLIT; ++q) {
        a += g_pacc[(size_t)(q * RT + mt) * BM * FO + row * FO + c];
        d += g_pden[(q * RT + mt) * BM + row];
    }
    float v = a / d;
    out[idx] = v > 0.f ? v : expm1f(v);
}

extern "C" void kernel_launch(void* const* d_in, const int* in_sizes, int n_in,
                              void* d_out, int out_size) {
    const float* h   = (const float*)d_in[0];
    const int*   adj = (const int*)d_in[1];
    const float* W   = (const float*)d_in[2];
    const float* a   = (const float*)d_in[3];
    float* out = (float*)d_out;

    wh_kernel<<<NN / 16, 256>>>(h, W);
    f12_kernel<<<NN / 4, 128>>>(a);

    cudaFuncSetAttribute(gat_mma, cudaFuncAttributeMaxDynamicSharedMemorySize, SM_TOTAL);
    gat_mma<<<dim3(RT, NSPLIT), 256, SM_TOTAL>>>(adj);

    combine_kernel<<<(NN * FO + 255) / 256, 256>>>(out);
}

// round 4
// speedup vs baseline: 2.1152x; 1.1569x over previous
#include <cuda_runtime.h>
#include <cuda_fp16.h>

#define NN 10000
#define FI 256
#define FO 64
#define BM 128
#define BN 64
#define NSPLIT 8
#define RT 79          // ceil(NN/BM)
#define NT 157         // ceil(NN/BN)
#define ALPHAS 0.2f

// ---------------- device scratch (no allocation allowed) ----------------
__device__ float g_Wh[NN * FO];
__device__ __half g_WhT[(size_t)FO * NN];     // n-major fp16 Wh^T
__device__ float g_f1[NN];
__device__ float g_f2[NN];
__device__ float g_pacc[(size_t)NSPLIT * RT * BM * FO];
__device__ float g_pden[NSPLIT * RT * BM];

// ---------------- smem layout (bytes) ----------------
#define PSTB 144                       // 128B data + 16B pad: conflict-free ldmatrix
#define SM_F2   0                      // 64 floats
#define SM_DEN  256                    // 128 floats
#define SM_P    768                    // 128 * 144
#define SM_B    (SM_P + BM * PSTB)     // 19200, 64 * 144
#define SM_TOTAL (SM_B + FO * PSTB)    // 28416

// ---------------- PTX helpers ----------------
__device__ __forceinline__ unsigned s2u(const void* p) {
    unsigned a;
    asm("{ .reg .u64 t; cvta.to.shared.u64 t, %1; cvt.u32.u64 %0, t; }"
        : "=r"(a) : "l"(p));
    return a;
}
__device__ __forceinline__ void ldsm4(unsigned* r, unsigned addr) {
    asm volatile("ldmatrix.sync.aligned.m8n8.x4.shared.b16 {%0,%1,%2,%3}, [%4];"
                 : "=r"(r[0]), "=r"(r[1]), "=r"(r[2]), "=r"(r[3]) : "r"(addr));
}
__device__ __forceinline__ void hmma(float* c, const unsigned* a, const unsigned* b) {
    asm volatile(
        "mma.sync.aligned.m16n8k16.row.col.f32.f16.f16.f32 "
        "{%0,%1,%2,%3}, {%4,%5,%6,%7}, {%8,%9}, {%0,%1,%2,%3};"
        : "+f"(c[0]), "+f"(c[1]), "+f"(c[2]), "+f"(c[3])
        : "r"(a[0]), "r"(a[1]), "r"(a[2]), "r"(a[3]), "r"(b[0]), "r"(b[1]));
}

// ---------------- Kernel 1: Wh = h @ W  (+ fp16 Wh^T) ----------------
__global__ __launch_bounds__(256) void wh_kernel(const float* __restrict__ h,
                                                 const float* __restrict__ W) {
    __shared__ float sh[16 * FI];
    int row0 = blockIdx.x * 16;
    const float* hp = h + (long long)row0 * FI;
    for (int t = threadIdx.x; t < 16 * FI; t += 256) sh[t] = hp[t];
    __syncthreads();
    int c = threadIdx.x & 63;
    int ty = threadIdx.x >> 6;   // 4 consecutive rows per thread
    float acc[4] = {0.f, 0.f, 0.f, 0.f};
    for (int k = 0; k < FI; ++k) {
        float w = W[k * FO + c];
        acc[0] += sh[(ty * 4 + 0) * FI + k] * w;
        acc[1] += sh[(ty * 4 + 1) * FI + k] * w;
        acc[2] += sh[(ty * 4 + 2) * FI + k] * w;
        acc[3] += sh[(ty * 4 + 3) * FI + k] * w;
    }
    __half hb[4];
    #pragma unroll
    for (int q = 0; q < 4; ++q) {
        int row = row0 + ty * 4 + q;
        g_Wh[row * FO + c] = acc[q];
        hb[q] = __float2half_rn(acc[q]);
    }
    size_t off = (size_t)c * NN + row0 + ty * 4;   // 4 consecutive j -> 8B store
    *(uint2*)&g_WhT[off] = *(uint2*)hb;
}

// ---------------- Kernel 2: f1/f2 ----------------
__global__ __launch_bounds__(128) void f12_kernel(const float* __restrict__ a) {
    int row = blockIdx.x * 4 + (threadIdx.x >> 5);
    int lane = threadIdx.x & 31;
    float w0 = g_Wh[row * FO + lane];
    float w1 = g_Wh[row * FO + 32 + lane];
    float s1 = w0 * a[lane] + w1 * a[lane + 32];
    float s2 = w0 * a[FO + lane] + w1 * a[FO + 32 + lane];
    #pragma unroll
    for (int o = 16; o > 0; o >>= 1) {
        s1 += __shfl_xor_sync(0xffffffffu, s1, o);
        s2 += __shfl_xor_sync(0xffffffffu, s2, o);
    }
    if (lane == 0) { g_f1[row] = s1; g_f2[row] = s2; }
}

// ---------------- Kernel 3: fused P-gen + single fp16 mma.sync GEMM ------
__global__ __launch_bounds__(256, 2) void gat_mma(const int* __restrict__ adj) {
    extern __shared__ char smem[];
    const unsigned sb = s2u(smem);
    float* sf2 = (float*)(smem + SM_F2);
    float* sden = (float*)(smem + SM_DEN);

    const int tid = threadIdx.x, wid = tid >> 5, lane = tid & 31;
    const int mt = blockIdx.x, jq = blockIdx.y;
    const int i0 = mt * BM;

    // P-gen mapping: thread -> (row r, 32-col half hh)
    const int r = tid >> 1, hh = tid & 1;
    const int i = i0 + r;
    const bool rowok = (i < NN);
    const float f1v = rowok ? g_f1[i] : 0.f;
    const int* arow = adj + (size_t)i * NN;

    // B-stage mapping: thread -> (c row, 16-half segment)
    const int bc = tid >> 2, bseg = tid & 3;

    // MMA fragment addressing
    const int m0 = wid * 16;
    const unsigned a_addr = sb + SM_P +
        (m0 + (lane & 7) + ((lane >> 3) & 1) * 8) * PSTB + (lane >> 4) * 16;
    const unsigned b_addr = sb + SM_B +
        ((lane & 7) + ((lane >> 4) & 1) * 8) * PSTB + ((lane >> 3) & 1) * 16;

    float acc[8][4];
    #pragma unroll
    for (int nt = 0; nt < 8; ++nt)
        #pragma unroll
        for (int q = 0; q < 4; ++q) acc[nt][q] = 0.f;

    if (tid < BM) sden[tid] = 0.f;

    for (int t = jq; t < NT; t += NSPLIT) {
        const int j0 = t * BN;

        // ---- prefetch adj into registers (overlaps prev tile's MMA) ----
        const int jb = j0 + hh * 32;
        int4 m[8];
        #pragma unroll
        for (int u = 0; u < 8; ++u) {
            bool ok = rowok && (jb + u * 4 + 3 < NN);
            m[u] = ok ? *(const int4*)(arow + jb + u * 4) : make_int4(0, 0, 0, 0);
        }

        __syncthreads();   // prev MMA done reading sP/sB

        // ---- stage B tile (WhT fp16, n-major, padded rows) + f2 ----
        #pragma unroll
        for (int ch = 0; ch < 2; ++ch) {
            int e0 = bseg * 16 + ch * 8;
            uint4 v = make_uint4(0, 0, 0, 0);
            if (j0 + e0 + 7 < NN)
                v = *(const uint4*)(g_WhT + (size_t)bc * NN + j0 + e0);
            *(uint4*)(smem + SM_B + bc * PSTB + e0 * 2) = v;
        }
        if (tid < BN) sf2[tid] = (j0 + tid < NN) ? g_f2[j0 + tid] : 0.f;
        __syncthreads();

        // ---- generate P tile (fp16) + denominator from ROUNDED p ----
        float rsum = 0.f;
        #pragma unroll
        for (int u = 0; u < 8; ++u) {
            float4 f2q = *(const float4*)&sf2[hh * 32 + u * 4];
            float s, p0, p1, p2, p3;
            s = f1v + f2q.x; s = fmaxf(s, ALPHAS * s); p0 = m[u].x ? __expf(s) : 0.f;
            s = f1v + f2q.y; s = fmaxf(s, ALPHAS * s); p1 = m[u].y ? __expf(s) : 0.f;
            s = f1v + f2q.z; s = fmaxf(s, ALPHAS * s); p2 = m[u].z ? __expf(s) : 0.f;
            s = f1v + f2q.w; s = fmaxf(s, ALPHAS * s); p3 = m[u].w ? __expf(s) : 0.f;
            __half2 h01 = __floats2half2_rn(p0, p1);
            __half2 h23 = __floats2half2_rn(p2, p3);
            *(uint2*)(smem + SM_P + r * PSTB + hh * 64 + u * 8) =
                make_uint2(*(unsigned*)&h01, *(unsigned*)&h23);
            // denominator uses the SAME rounded values the MMA will see
            float2 b01 = __half22float2(h01);
            float2 b23 = __half22float2(h23);
            rsum += (b01.x + b01.y) + (b23.x + b23.y);
        }
        rsum += __shfl_down_sync(0xffffffffu, rsum, 1);
        if (!hh) sden[r] += rsum;   // unique owner thread per row
        __syncthreads();

        // ---- MMA: C += P @ WhT (single fp16 product) ----
        #pragma unroll
        for (int ks = 0; ks < 4; ++ks) {
            unsigned a[4];
            ldsm4(a, a_addr + ks * 32);
            unsigned b[16];
            #pragma unroll
            for (int q = 0; q < 4; ++q)
                ldsm4(b + 4 * q, b_addr + q * 16 * PSTB + ks * 32);
            #pragma unroll
            for (int nt = 0; nt < 8; ++nt)
                hmma(acc[nt], a, b + nt * 2);
        }
    }
    __syncthreads();

    // ---- epilogue: write register partials ----
    {
        float* pa = g_pacc + (size_t)(jq * RT + mt) * BM * FO;
        int row = m0 + (lane >> 2);
        int col = (lane & 3) * 2;
        #pragma unroll
        for (int nt = 0; nt < 8; ++nt) {
            *(float2*)&pa[row * FO + nt * 8 + col] = make_float2(acc[nt][0], acc[nt][1]);
            *(float2*)&pa[(row + 8) * FO + nt * 8 + col] = make_float2(acc[nt][2], acc[nt][3]);
        }
    }
    if (tid < BM) g_pden[(jq * RT + mt) * BM + tid] = sden[tid];
}

// ---------------- Kernel 4: combine partials + ELU ----------------
__global__ __launch_bounds__(256) void combine_kernel(float* __restrict__ out) {
    int idx = blockIdx.x * 256 + threadIdx.x;
    if (idx >= NN * FO) return;
    int i = idx >> 6, c = idx & 63;
    int mt = i >> 7, row = i & 127;
    float a = 0.f, d = 0.f;
    #pragma unroll
    for (int q = 0; q < NSPLIT; ++q) {
        a += g_pacc[(size_t)(q * RT + mt) * BM * FO + row * FO + c];
        d += g_pden[(q * RT + mt) * BM + row];
    }
    float v = a / d;
    out[idx] = v > 0.f ? v : expm1f(v);
}

extern "C" void kernel_launch(void* const* d_in, const int* in_sizes, int n_in,
                              void* d_out, int out_size) {
    const float* h   = (const float*)d_in[0];
    const int*   adj = (const int*)d_in[1];
    const float* W   = (const float*)d_in[2];
    const float* a   = (const float*)d_in[3];
    float* out = (float*)d_out;

    wh_kernel<<<NN / 16, 256>>>(h, W);
    f12_kernel<<<NN / 4, 128>>>(a);
    gat_mma<<<dim3(RT, NSPLIT), 256, SM_TOTAL>>>(adj);
    combine_kernel<<<(NN * FO + 255) / 256, 256>>>(out);
}